// round 11
// baseline (speedup 1.0000x reference)
#include <cuda_runtime.h>
#include <cstdint>

// Batched OSQP ADMM: B=64, n=256, m=512, 200 iterations.
// Reformulated loop (sigma*x term dropped, ~1e-5 rel effect):
//   w = rho*z - y; t = H w; z~ = z0 + A t; z/y updates; sx = (1-a)sx + a*t
//   with H = Minv A^T, x0 = -Minv q, z0 = A x0, x_final = x0 + sx.
// setup1: syrk  M = rho*A'A + diag(P)+sigma
// setup2: Cholesky + W=L^T + single-RHS solve for x0
// solve:  H columns via fwd/bwd triangular solves, 8 blocks/batch
// admm:   2-CTA cluster per batch, 1024 thr, 2 GEMVs + 2 cluster barriers/iter,
//         208KB/CTA of H/A cached in SMEM, remainder streamed L2 (ldcg).

#define NBAT 64
#define NV   256
#define MCON 512

__device__ float g_M [(size_t)NBAT*NV*NV];     // M, then L (col-major lower)
__device__ float g_W [(size_t)NBAT*NV*NV];     // L row-major
__device__ float g_H [(size_t)NBAT*NV*MCON];   // H = Minv A^T, row-major 256x512
__device__ float g_x0[(size_t)NBAT*NV];        // -Minv q
__device__ float g_state[(size_t)NBAT*1280];   // sx 256 | z 512 | y 512

__device__ __forceinline__ void dot4(float4& a, const float4 v, const float4 s) {
    a.x = fmaf(v.x, s.x, a.x); a.y = fmaf(v.y, s.y, a.y);
    a.z = fmaf(v.z, s.z, a.z); a.w = fmaf(v.w, s.w, a.w);
}
__device__ __forceinline__ uint32_t mapa_u32(uint32_t laddr, uint32_t rank) {
    uint32_t ra;
    asm("mapa.shared::cluster.u32 %0, %1, %2;" : "=r"(ra) : "r"(laddr), "r"(rank));
    return ra;
}
__device__ __forceinline__ void st_cluster_f32(uint32_t addr, float v) {
    asm volatile("st.shared::cluster.f32 [%0], %1;" :: "r"(addr), "f"(v) : "memory");
}
#define CLUSTER_ARRIVE() asm volatile("barrier.cluster.arrive.aligned;" ::: "memory")
#define CLUSTER_WAIT()   asm volatile("barrier.cluster.wait.aligned;"   ::: "memory")

// ---------------------------------------------------------------------------
// setup1: syrk 64x64 tile pairs, 10 blocks per batch.
// ---------------------------------------------------------------------------
__global__ void __launch_bounds__(256) setup1_kernel(const float* __restrict__ A,
                                                     const float* __restrict__ P)
{
    const int pr = blockIdx.x, b = blockIdx.y;
    const int tid = threadIdx.x;
    int ti, tj;
    if      (pr < 4) { ti = 0; tj = pr;     }
    else if (pr < 7) { ti = 1; tj = pr - 3; }
    else if (pr < 9) { ti = 2; tj = pr - 5; }
    else             { ti = 3; tj = 3;      }

    __shared__ float As[16 * 64], Bs[16 * 64];
    const float* Ab = A + (size_t)b * MCON * NV;
    const int lr = tid >> 4, lc = tid & 15;

    float acc[4][4] = {};
    for (int k0 = 0; k0 < MCON; k0 += 16) {
        *(float4*)(As + lr*64 + lc*4) = *(const float4*)(Ab + (size_t)(k0+lr)*NV + ti*64 + lc*4);
        *(float4*)(Bs + lr*64 + lc*4) = *(const float4*)(Ab + (size_t)(k0+lr)*NV + tj*64 + lc*4);
        __syncthreads();
#pragma unroll
        for (int kk = 0; kk < 16; kk++) {
            float4 a4 = *(float4*)(As + kk*64 + lr*4);
            float4 b4 = *(float4*)(Bs + kk*64 + lc*4);
            float av[4] = {a4.x, a4.y, a4.z, a4.w};
            float bv[4] = {b4.x, b4.y, b4.z, b4.w};
#pragma unroll
            for (int r = 0; r < 4; r++)
#pragma unroll
                for (int s = 0; s < 4; s++)
                    acc[r][s] = fmaf(av[r], bv[s], acc[r][s]);
        }
        __syncthreads();
    }

    float* Mb = g_M + (size_t)b * NV * NV;
    const float RHO = 0.1f, SIGMA = 1e-6f;
#pragma unroll
    for (int r = 0; r < 4; r++)
#pragma unroll
        for (int s = 0; s < 4; s++) {
            int i = ti*64 + lr*4 + r;
            int j = tj*64 + lc*4 + s;
            float v = RHO * acc[r][s];
            if (i == j) v += P[b*NV + i] + SIGMA;
            Mb[(size_t)i*NV + j] = v;
            if (ti != tj) Mb[(size_t)j*NV + i] = v;
        }
}

// ---------------------------------------------------------------------------
// setup2: Cholesky (1024 thr, 4-way k-split), W = L row-major, x0 = -Minv q.
// ---------------------------------------------------------------------------
__global__ void __launch_bounds__(1024) setup2_kernel(const float* __restrict__ qv)
{
    const int b = blockIdx.x, tid = threadIdx.x;
    const int r = tid & 255, s = tid >> 8;
    float* M = g_M + (size_t)b * NV * NV;
    extern __shared__ float Lc[];                // 192*256
    __shared__ float psum[1024];
    __shared__ float st[32][33];
    __shared__ float rds[256];
    __shared__ float vv[256];
    __shared__ float sdiag;

    for (int j = 0; j < NV; j++) {
        float acc = 0.0f;
        const int kc = j < 192 ? j : 192;
#pragma unroll 4
        for (int k = s; k < kc; k += 4)
            acc -= Lc[k*NV + r] * Lc[k*NV + j];
        for (int k = 192 + s; k < j; k += 4)
            acc -= M[(size_t)k*NV + r] * M[(size_t)k*NV + j];
        psum[tid] = acc;
        __syncthreads();
        float a = 0.0f;
        if (s == 0) {
            a = M[(size_t)j*NV + r] + psum[r] + psum[r+256] + psum[r+512] + psum[r+768];
            if (r == j) sdiag = a;
        }
        __syncthreads();
        if (s == 0 && r >= j) {
            float val = a * rsqrtf(sdiag);
            M[(size_t)j*NV + r] = val;
            if (j < 192) Lc[j*NV + r] = val;
        }
        __syncthreads();
    }

    // W = L row-major via conflict-free tile transposes
    float* W = g_W + (size_t)b * NV * NV;
    const int ty = tid >> 5, tx = tid & 31;
    for (int k0 = 0; k0 < NV; k0 += 32) {
        for (int i0 = 0; i0 < NV; i0 += 32) {
            st[ty][tx] = (k0 + ty < 192) ? Lc[(k0+ty)*NV + i0 + tx]
                                         : M[(size_t)(k0+ty)*NV + i0 + tx];
            __syncthreads();
            W[(size_t)(i0+ty)*NV + k0 + tx] = st[tx][ty];
            __syncthreads();
        }
    }

    // x0 = -Minv q: fwd/bwd solve, single RHS, unscaled accumulators.
    if (tid < NV) { rds[tid] = 1.0f / M[(size_t)tid*NV + tid]; vv[tid] = qv[b*NV + tid]; }
    __syncthreads();
    for (int j = 0; j < NV; j++) {
        float yj = vv[j] * rds[j];
        __syncthreads();
        if (tid < NV && tid > j) {
            float lv = (j < 192) ? Lc[j*NV + tid] : M[(size_t)j*NV + tid];
            vv[tid] = fmaf(-lv, yj, vv[tid]);
        }
        __syncthreads();
    }
    if (tid < NV) vv[tid] *= rds[tid];
    __syncthreads();
    for (int j = NV - 1; j >= 0; j--) {
        float xj = vv[j] * rds[j];
        __syncthreads();
        if (tid < j)
            vv[tid] = fmaf(-W[(size_t)j*NV + tid], xj, vv[tid]);
        __syncthreads();
    }
    if (tid < NV) g_x0[b*NV + tid] = -(vv[tid] * rds[tid]);
}

// ---------------------------------------------------------------------------
// solve: block (g, b) computes 64 columns [g*64, +64) of H = Minv A^T by
// solving M X = A^T column-block. 1024 threads, Y 256x64 in SMEM, 32-row
// L panels. Unscaled-accumulator form: one sync per step.
// ---------------------------------------------------------------------------
__global__ void __launch_bounds__(1024) solve_kernel(const float* __restrict__ A)
{
    const int g = blockIdx.x, b = blockIdx.y, tid = threadIdx.x;
    extern __shared__ float sm[];
    float* Yf = sm;            // 16384 (256 rows x 64 cols)
    float* Lp = sm + 16384;    // 8192 (32 rows x 256)
    float* rd = sm + 24576;    // 256
    const float* M  = g_M + (size_t)b * NV * NV;
    const float* Wt = g_W + (size_t)b * NV * NV;
    const float* Ab = A + (size_t)b * MCON * NV;

    if (tid < NV) rd[tid] = 1.0f / M[(size_t)tid*NV + tid];
    // Y[i][jj] = A^T[i, g*64+jj] = A[g*64+jj][i]
    for (int idx = tid; idx < 16384; idx += 1024) {
        const int i = idx >> 6, jj = idx & 63;
        Yf[idx] = Ab[(size_t)(g*64 + jj)*NV + i];
    }
    const int qd = tid >> 5, c2 = tid & 31;
    float2* Y2 = (float2*)Yf;

    // forward: L Y = RHS (accumulators unscaled; scale on the fly)
    for (int i = 0; i < NV; i++) {
        if ((i & 31) == 0) {
            __syncthreads();
            for (int idx = tid; idx < 8192; idx += 1024)
                Lp[idx] = M[(size_t)(i + (idx >> 8)) * NV + (idx & 255)];
        }
        __syncthreads();
        float2 yv = Y2[i*32 + c2];
        const float sc = rd[i];
        const float yx = yv.x * sc, yy = yv.y * sc;
        const float* lcol = Lp + (i & 31) * NV;
        for (int i2 = i + 1 + ((qd - (i + 1)) & 31); i2 < NV; i2 += 32) {
            float lv = lcol[i2];
            float2 t = Y2[i2*32 + c2];
            t.x = fmaf(-lv, yx, t.x);
            t.y = fmaf(-lv, yy, t.y);
            Y2[i2*32 + c2] = t;
        }
    }
    __syncthreads();
    for (int idx = tid; idx < 16384; idx += 1024)
        Yf[idx] *= rd[idx >> 6];

    // backward: L^T X = Y
    for (int i = NV - 1; i >= 0; i--) {
        if ((i & 31) == 31) {
            __syncthreads();
            const int p = i - 31;
            for (int idx = tid; idx < 8192; idx += 1024)
                Lp[idx] = Wt[(size_t)(p + (idx >> 8)) * NV + (idx & 255)];
        }
        __syncthreads();
        float2 xv = Y2[i*32 + c2];
        const float sc = rd[i];
        const float xx = xv.x * sc, xy = xv.y * sc;
        const float* lrow = Lp + (i & 31) * NV;
        for (int i2 = qd; i2 < i; i2 += 32) {
            float lv = lrow[i2];
            float2 t = Y2[i2*32 + c2];
            t.x = fmaf(-lv, xx, t.x);
            t.y = fmaf(-lv, xy, t.y);
            Y2[i2*32 + c2] = t;
        }
    }
    __syncthreads();
    float* Hb = g_H + (size_t)b * NV * MCON;
    for (int idx = tid; idx < 16384; idx += 1024) {
        const int i = idx >> 6, jj = idx & 63;
        Hb[(size_t)i*MCON + g*64 + jj] = Yf[idx] * rd[i];
    }
}

__global__ void noop_kernel() {}

// ---------------------------------------------------------------------------
// admm: 2-CTA cluster per batch, 1024 thr, 100 iterations per launch.
// ---------------------------------------------------------------------------
__global__ void __launch_bounds__(1024, 1) __cluster_dims__(2, 1, 1)
admm_kernel(const float* __restrict__ A, const float* __restrict__ l,
            const float* __restrict__ u, float* __restrict__ out, int phase)
{
    const int b = blockIdx.x >> 1, r = blockIdx.x & 1;
    const int tid = threadIdx.x;
    extern __shared__ float sh[];
    float4* Hs4 = (float4*)sh;               // 52 H-rows x 128 f4
    float4* As4 = (float4*)(sh + 26624);     // 104 A-rows x 64 f4 (swizzled)
    float*  w_s = sh + 53248;                // 512 (full w)
    float*  t_s = sh + 53760;                // 256 (full t / x0)
    // total 54016 floats = 216064 B

    const float RHO = 0.1f, ALPHA = 1.6f, OMA = -0.6f;
    const float4* A4g = (const float4*)(A + (size_t)b * MCON * NV);
    const float4* H4g = (const float4*)(g_H + (size_t)b * NV * MCON);
    const float4* w4s = (const float4*)w_s;
    const float4* t4s = (const float4*)t_s;

    // SMEM caches
    for (int i4 = tid; i4 < 52*128; i4 += 1024)
        Hs4[i4] = H4g[(size_t)(r*128 + (i4 >> 7))*128 + (i4 & 127)];
    for (int i4 = tid; i4 < 104*64; i4 += 1024) {
        const int rb = i4 >> 6, c = i4 & 63;
        As4[rb*64 + (c ^ ((rb & 1) << 5))] = A4g[(size_t)(r*256 + rb)*64 + c];
    }

    const int rowL = tid >> 3, lane8 = tid & 7;   // phase A: 128 rows x 8
    const int rowB = tid >> 2, qu = tid & 3;      // phase B: 256 rows x 4
    const int mg = r*256 + rowB;
    const bool ownA = (lane8 == 0), ownB = (qu == 0);

    float* st = g_state + (size_t)b * 1280;
    float sx = 0.f, z_r = 0.f, y_r = 0.f, l_r = 0.f, u_r = 0.f, z0_r = 0.f;

    const uint32_t peer = (uint32_t)(r ^ 1);
    uint32_t ra_t = 0, ra_w = 0;
    if (ownA) {
        ra_t = mapa_u32((uint32_t)__cvta_generic_to_shared(t_s + r*128 + rowL), peer);
        if (phase) sx = st[r*128 + rowL];
    }
    if (ownB) {
        ra_w = mapa_u32((uint32_t)__cvta_generic_to_shared(w_s + mg), peer);
        l_r = l[b*MCON + mg]; u_r = u[b*MCON + mg];
        if (phase) { z_r = st[256 + mg]; y_r = st[768 + mg]; }
        float w0 = fmaf(RHO, z_r, -y_r);
        w_s[mg] = w0;
        st_cluster_f32(ra_w, w0);
    }
    if (tid < NV) t_s[tid] = g_x0[b*NV + tid];    // x0 for z0 pass
    __syncthreads();

    // z0 pass: z0_own = A_own * x0 (same code path as phase B)
    {
        float4 a0 = {0,0,0,0}, a1 = {0,0,0,0};
        if (rowB < 104) {
            const float4* Arow = As4 + rowB*64;
            const int sw = (rowB & 1) << 5;
#pragma unroll
            for (int t = 0; t < 16; t += 2) {
                dot4(a0, Arow[(qu + 4*t) ^ sw],       t4s[qu + 4*t]);
                dot4(a1, Arow[(qu + 4*(t+1)) ^ sw],   t4s[qu + 4*(t+1)]);
            }
        } else {
            const float4* Arow = A4g + (size_t)(r*256 + rowB)*64;
#pragma unroll
            for (int t = 0; t < 16; t += 2) {
                dot4(a0, __ldcg(Arow + qu + 4*t),     t4s[qu + 4*t]);
                dot4(a1, __ldcg(Arow + qu + 4*(t+1)), t4s[qu + 4*(t+1)]);
            }
        }
        float sB = (a0.x+a0.y)+(a0.z+a0.w)+(a1.x+a1.y)+(a1.z+a1.w);
        sB += __shfl_xor_sync(0xffffffffu, sB, 1);
        sB += __shfl_xor_sync(0xffffffffu, sB, 2);
        if (ownB) z0_r = sB;
    }
    CLUSTER_ARRIVE();
    CLUSTER_WAIT();

    for (int it = 0; it < 100; it++) {
        // ---- Phase A: t = H w (own 128 t-rows) ----
        float4 acc0 = {0,0,0,0}, acc1 = {0,0,0,0};
        if (rowL < 52) {
            const float4* Hrow = Hs4 + rowL*128;
#pragma unroll
            for (int t = 0; t < 16; t += 2) {
                dot4(acc0, Hrow[lane8 + 8*t],             w4s[lane8 + 8*t]);
                dot4(acc1, Hrow[lane8 + 8*(t+1)],         w4s[lane8 + 8*(t+1)]);
            }
        } else {
            const float4* Hrow = H4g + (size_t)(r*128 + rowL)*128;
#pragma unroll
            for (int t = 0; t < 16; t += 2) {
                dot4(acc0, __ldcg(Hrow + lane8 + 8*t),    w4s[lane8 + 8*t]);
                dot4(acc1, __ldcg(Hrow + lane8 + 8*(t+1)), w4s[lane8 + 8*(t+1)]);
            }
        }
        float sA = (acc0.x+acc0.y)+(acc0.z+acc0.w)+(acc1.x+acc1.y)+(acc1.z+acc1.w);
        sA += __shfl_xor_sync(0xffffffffu, sA, 1);
        sA += __shfl_xor_sync(0xffffffffu, sA, 2);
        sA += __shfl_xor_sync(0xffffffffu, sA, 4);
        if (ownA) {
            sx = fmaf(OMA, sx, ALPHA * sA);
            t_s[r*128 + rowL] = sA;
            st_cluster_f32(ra_t, sA);
        }
        CLUSTER_ARRIVE();
        CLUSTER_WAIT();

        // ---- Phase B: z~ = z0 + A t (own 256 m-rows) ----
        float4 a0 = {0,0,0,0}, a1 = {0,0,0,0};
        if (rowB < 104) {
            const float4* Arow = As4 + rowB*64;
            const int sw = (rowB & 1) << 5;
#pragma unroll
            for (int t = 0; t < 16; t += 2) {
                dot4(a0, Arow[(qu + 4*t) ^ sw],       t4s[qu + 4*t]);
                dot4(a1, Arow[(qu + 4*(t+1)) ^ sw],   t4s[qu + 4*(t+1)]);
            }
        } else {
            const float4* Arow = A4g + (size_t)(r*256 + rowB)*64;
#pragma unroll
            for (int t = 0; t < 16; t += 2) {
                dot4(a0, __ldcg(Arow + qu + 4*t),     t4s[qu + 4*t]);
                dot4(a1, __ldcg(Arow + qu + 4*(t+1)), t4s[qu + 4*(t+1)]);
            }
        }
        float sB = (a0.x+a0.y)+(a0.z+a0.w)+(a1.x+a1.y)+(a1.z+a1.w);
        sB += __shfl_xor_sync(0xffffffffu, sB, 1);
        sB += __shfl_xor_sync(0xffffffffu, sB, 2);
        if (ownB) {
            float zt = z0_r + sB;
            float zr = fmaf(ALPHA, zt, OMA * z_r);
            float zc = fminf(fmaxf(fmaf(y_r, 10.0f, zr), l_r), u_r);  // 1/RHO=10
            y_r = fmaf(RHO, zr - zc, y_r);
            z_r = zc;
            float w = fmaf(RHO, z_r, -y_r);
            w_s[mg] = w;
            st_cluster_f32(ra_w, w);
        }
        CLUSTER_ARRIVE();
        CLUSTER_WAIT();
    }

    if (phase == 0) {
        if (ownB) { st[256 + mg] = z_r; st[768 + mg] = y_r; }
        if (ownA) st[r*128 + rowL] = sx;
    } else {
        if (ownA)
            out[b*NV + r*128 + rowL] = g_x0[b*NV + r*128 + rowL] + sx;
    }
}

// ---------------------------------------------------------------------------
extern "C" void kernel_launch(void* const* d_in, const int* in_sizes, int n_in,
                              void* d_out, int out_size)
{
    const float* P = (const float*)d_in[0];
    const float* q = (const float*)d_in[1];
    const float* A = (const float*)d_in[2];
    const float* l = (const float*)d_in[3];
    const float* u = (const float*)d_in[4];
    float* out = (float*)d_out;

    const int CHOL_SMEM  = 192 * 256 * 4;                // 196608
    const int SOLVE_SMEM = (16384 + 8192 + 256) * 4;     // 99328
    const int ADMM_SMEM  = 54016 * 4;                    // 216064
    cudaFuncSetAttribute(setup2_kernel, cudaFuncAttributeMaxDynamicSharedMemorySize, CHOL_SMEM);
    cudaFuncSetAttribute(solve_kernel,  cudaFuncAttributeMaxDynamicSharedMemorySize, SOLVE_SMEM);
    cudaFuncSetAttribute(admm_kernel,   cudaFuncAttributeMaxDynamicSharedMemorySize, ADMM_SMEM);

    setup1_kernel<<<dim3(10, NBAT), 256>>>(A, P);
    setup2_kernel<<<NBAT, 1024, CHOL_SMEM>>>(q);
    solve_kernel<<<dim3(8, NBAT), 1024, SOLVE_SMEM>>>(A);
    admm_kernel<<<2 * NBAT, 1024, ADMM_SMEM>>>(A, l, u, out, 0);
    noop_kernel<<<1, 32>>>();
    admm_kernel<<<2 * NBAT, 1024, ADMM_SMEM>>>(A, l, u, out, 1);
}

// round 12
// speedup vs baseline: 1.0105x; 1.0105x over previous
#include <cuda_runtime.h>
#include <cstdint>

// Batched OSQP ADMM: B=64, n=256, m=512, 200 iterations.
// Reformulation: G = A Minv A^T; loop is z~ = z0 + G w (one GEMV) + elementwise;
// sacc accumulates alpha-weighted w's; x = x0 + Minv A^T sacc at the end.
// setup1: syrk  M = rho*A'A + diag(P)+sigma
// setup2: Cholesky + W=L^T + x0 = -Minv q
// csolve: C = L^{-1} A^T, blocked trsm (32-row panels + register-tiled updates)
// gsyrk:  G = C^T C  via Ct row-row GEMM (128x128 tiles, mirrored pairs)
// admm2:  2-CTA cluster/batch, 1024 thr, ONE GEMV + ONE cluster barrier/iter,
//         double-buffered w exchange, 104 G-rows in SMEM, rest L2-streamed.
// finish: v = A^T sacc; solve M xh = v; out = x0 + xh.

#define NBAT 64
#define NV   256
#define MCON 512

__device__ float g_M [(size_t)NBAT*NV*NV];      // M, then L (col-major lower)
__device__ float g_W [(size_t)NBAT*NV*NV];      // L row-major
__device__ float g_Ct[(size_t)NBAT*MCON*NV];    // Ct[m][k] = (L^{-1}A^T)[k][m]
__device__ float g_G [(size_t)NBAT*MCON*MCON];  // G = A Minv A^T, row-major
__device__ float g_x0[(size_t)NBAT*NV];         // -Minv q
__device__ float g_state[(size_t)NBAT*2048];    // sacc 512 | z 512 | y 512 | z0 512

__device__ __forceinline__ void fma4(float4& a, const float4 v, const float s) {
    a.x = fmaf(v.x, s, a.x); a.y = fmaf(v.y, s, a.y);
    a.z = fmaf(v.z, s, a.z); a.w = fmaf(v.w, s, a.w);
}
__device__ __forceinline__ void dot4(float4& a, const float4 v, const float4 s) {
    a.x = fmaf(v.x, s.x, a.x); a.y = fmaf(v.y, s.y, a.y);
    a.z = fmaf(v.z, s.z, a.z); a.w = fmaf(v.w, s.w, a.w);
}
__device__ __forceinline__ uint32_t mapa_u32(uint32_t laddr, uint32_t rank) {
    uint32_t ra;
    asm("mapa.shared::cluster.u32 %0, %1, %2;" : "=r"(ra) : "r"(laddr), "r"(rank));
    return ra;
}
__device__ __forceinline__ void st_cluster_f32(uint32_t addr, float v) {
    asm volatile("st.shared::cluster.f32 [%0], %1;" :: "r"(addr), "f"(v) : "memory");
}
#define CLUSTER_ARRIVE() asm volatile("barrier.cluster.arrive.aligned;" ::: "memory")
#define CLUSTER_WAIT()   asm volatile("barrier.cluster.wait.aligned;"   ::: "memory")

// ---------------------------------------------------------------------------
// setup1: syrk 64x64 tile pairs, 10 blocks per batch.
// ---------------------------------------------------------------------------
__global__ void __launch_bounds__(256) setup1_kernel(const float* __restrict__ A,
                                                     const float* __restrict__ P)
{
    const int pr = blockIdx.x, b = blockIdx.y;
    const int tid = threadIdx.x;
    int ti, tj;
    if      (pr < 4) { ti = 0; tj = pr;     }
    else if (pr < 7) { ti = 1; tj = pr - 3; }
    else if (pr < 9) { ti = 2; tj = pr - 5; }
    else             { ti = 3; tj = 3;      }

    __shared__ float As[16 * 64], Bs[16 * 64];
    const float* Ab = A + (size_t)b * MCON * NV;
    const int lr = tid >> 4, lc = tid & 15;

    float acc[4][4] = {};
    for (int k0 = 0; k0 < MCON; k0 += 16) {
        *(float4*)(As + lr*64 + lc*4) = *(const float4*)(Ab + (size_t)(k0+lr)*NV + ti*64 + lc*4);
        *(float4*)(Bs + lr*64 + lc*4) = *(const float4*)(Ab + (size_t)(k0+lr)*NV + tj*64 + lc*4);
        __syncthreads();
#pragma unroll
        for (int kk = 0; kk < 16; kk++) {
            float4 a4 = *(float4*)(As + kk*64 + lr*4);
            float4 b4 = *(float4*)(Bs + kk*64 + lc*4);
            float av[4] = {a4.x, a4.y, a4.z, a4.w};
            float bv[4] = {b4.x, b4.y, b4.z, b4.w};
#pragma unroll
            for (int r = 0; r < 4; r++)
#pragma unroll
                for (int s = 0; s < 4; s++)
                    acc[r][s] = fmaf(av[r], bv[s], acc[r][s]);
        }
        __syncthreads();
    }

    float* Mb = g_M + (size_t)b * NV * NV;
    const float RHO = 0.1f, SIGMA = 1e-6f;
#pragma unroll
    for (int r = 0; r < 4; r++)
#pragma unroll
        for (int s = 0; s < 4; s++) {
            int i = ti*64 + lr*4 + r;
            int j = tj*64 + lc*4 + s;
            float v = RHO * acc[r][s];
            if (i == j) v += P[b*NV + i] + SIGMA;
            Mb[(size_t)i*NV + j] = v;
            if (ti != tj) Mb[(size_t)j*NV + i] = v;
        }
}

// ---------------------------------------------------------------------------
// setup2: Cholesky (1024 thr, 4-way k-split), W = L row-major, x0 = -Minv q.
// ---------------------------------------------------------------------------
__global__ void __launch_bounds__(1024) setup2_kernel(const float* __restrict__ qv)
{
    const int b = blockIdx.x, tid = threadIdx.x;
    const int r = tid & 255, s = tid >> 8;
    float* M = g_M + (size_t)b * NV * NV;
    extern __shared__ float Lc[];                // 192*256
    __shared__ float psum[1024];
    __shared__ float st[32][33];
    __shared__ float rds[256];
    __shared__ float vv[256];
    __shared__ float sdiag;

    for (int j = 0; j < NV; j++) {
        float acc = 0.0f;
        const int kc = j < 192 ? j : 192;
#pragma unroll 4
        for (int k = s; k < kc; k += 4)
            acc -= Lc[k*NV + r] * Lc[k*NV + j];
        for (int k = 192 + s; k < j; k += 4)
            acc -= M[(size_t)k*NV + r] * M[(size_t)k*NV + j];
        psum[tid] = acc;
        __syncthreads();
        float a = 0.0f;
        if (s == 0) {
            a = M[(size_t)j*NV + r] + psum[r] + psum[r+256] + psum[r+512] + psum[r+768];
            if (r == j) sdiag = a;
        }
        __syncthreads();
        if (s == 0 && r >= j) {
            float val = a * rsqrtf(sdiag);
            M[(size_t)j*NV + r] = val;
            if (j < 192) Lc[j*NV + r] = val;
        }
        __syncthreads();
    }

    // W = L row-major via conflict-free tile transposes
    float* W = g_W + (size_t)b * NV * NV;
    const int ty = tid >> 5, tx = tid & 31;
    for (int k0 = 0; k0 < NV; k0 += 32) {
        for (int i0 = 0; i0 < NV; i0 += 32) {
            st[ty][tx] = (k0 + ty < 192) ? Lc[(k0+ty)*NV + i0 + tx]
                                         : M[(size_t)(k0+ty)*NV + i0 + tx];
            __syncthreads();
            W[(size_t)(i0+ty)*NV + k0 + tx] = st[tx][ty];
            __syncthreads();
        }
    }

    // x0 = -Minv q: fwd/bwd solve, single RHS, unscaled accumulators.
    if (tid < NV) { rds[tid] = 1.0f / M[(size_t)tid*NV + tid]; vv[tid] = qv[b*NV + tid]; }
    __syncthreads();
    for (int j = 0; j < NV; j++) {
        float yj = vv[j] * rds[j];
        __syncthreads();
        if (tid < NV && tid > j) {
            float lv = (j < 192) ? Lc[j*NV + tid] : M[(size_t)j*NV + tid];
            vv[tid] = fmaf(-lv, yj, vv[tid]);
        }
        __syncthreads();
    }
    if (tid < NV) vv[tid] *= rds[tid];
    __syncthreads();
    for (int j = NV - 1; j >= 0; j--) {
        float xj = vv[j] * rds[j];
        __syncthreads();
        if (tid < j)
            vv[tid] = fmaf(-W[(size_t)j*NV + tid], xj, vv[tid]);
        __syncthreads();
    }
    if (tid < NV) g_x0[b*NV + tid] = -(vv[tid] * rds[tid]);
}

// ---------------------------------------------------------------------------
// csolve: block (g, b) computes 64 columns [g*64,+64) of C = L^{-1} A^T via
// blocked forward trsm: 32-row serial panels + register-tiled GEMM updates.
// Writes Ct (transposed) to g_Ct.
// ---------------------------------------------------------------------------
__global__ void __launch_bounds__(1024) csolve_kernel(const float* __restrict__ A)
{
    const int g = blockIdx.x, b = blockIdx.y, tid = threadIdx.x;
    extern __shared__ float sm[];
    float* Yf   = sm;                 // 16384 (256 x 64)
    float* Lg   = sm + 16384;         // 7168  (32 x 224)
    float* Ys   = sm + 23552;         // 2176  (32 x 68, scaled panel)
    float* Ld   = sm + 25728;         // 1056  (32 x 33 diag block)
    float* rd   = sm + 26784;         // 256
    float* tile = sm + 27040;         // 1056  (32 x 33 transpose staging)
    // total 28096 floats = 112384 B

    const float* M  = g_M + (size_t)b * NV * NV;
    const float* Ab = A + (size_t)b * MCON * NV;
    float2* Y2 = (float2*)Yf;
    float4* Yf4 = (float4*)Yf;
    const float4* Ys4 = (const float4*)Ys;

    if (tid < NV) rd[tid] = 1.0f / M[(size_t)tid*NV + tid];
    for (int idx = tid; idx < 16384; idx += 1024) {
        const int i = idx >> 6, jj = idx & 63;
        Yf[idx] = Ab[(size_t)(g*64 + jj)*NV + i];
    }
    __syncthreads();

    const int qd = tid >> 5, c2 = tid & 31;       // panel solve map
    const int rowg = tid >> 4, colg = tid & 15;   // GEMM update map

    for (int p = 0; p < 8; p++) {
        const int P0 = 32 * p;
        // diag block: Ld[j][i2] = L[P0+i2, P0+j] = M[(P0+j)*256 + P0+i2]
        {
            const int j = tid >> 5, i2 = tid & 31;
            Ld[j*33 + i2] = M[(size_t)(P0 + j)*NV + P0 + i2];
        }
        __syncthreads();

        // serial panel solve (unscaled accumulators)
        for (int li = 0; li < 32; li++) {
            const int i = P0 + li;
            float2 yv = Y2[i*32 + c2];
            const float sc = rd[i];
            yv.x *= sc; yv.y *= sc;
            if (qd > li) {
                const float lv = Ld[li*33 + qd];
                float2 t = Y2[(P0 + qd)*32 + c2];
                t.x = fmaf(-lv, yv.x, t.x);
                t.y = fmaf(-lv, yv.y, t.y);
                Y2[(P0 + qd)*32 + c2] = t;
            }
            __syncthreads();
        }

        if (p < 7) {
            const int R = 224 - 32*p;
            // scaled panel Ys[k][j]
            for (int e = tid; e < 2048; e += 1024) {
                const int k = e >> 6, j = e & 63;
                Ys[k*68 + j] = Yf[(P0 + k)*64 + j] * rd[P0 + k];
            }
            // Lg[k][ir] = L[P0+32+ir, P0+k] = M[(P0+k)*256 + P0+32+ir]
            for (int e = tid; e < 32*R; e += 1024) {
                const int k = e / R, ir = e - k*R;
                Lg[k*224 + ir] = M[(size_t)(P0 + k)*NV + P0 + 32 + ir];
            }
            __syncthreads();

            // register-tiled update: Y[P0+32+i2r] -= sum_k L * Ys
#pragma unroll
            for (int rrr = 0; rrr < 4; rrr++) {
                const int i2r = rowg + 64*rrr;
                if (i2r < R) {
                    const int i2 = P0 + 32 + i2r;
                    float4 acc = Yf4[i2*16 + colg];
#pragma unroll
                    for (int k = 0; k < 32; k++) {
                        const float lv = Lg[k*224 + i2r];
                        const float4 yv = Ys4[k*17 + colg];
                        acc.x = fmaf(-lv, yv.x, acc.x);
                        acc.y = fmaf(-lv, yv.y, acc.y);
                        acc.z = fmaf(-lv, yv.z, acc.z);
                        acc.w = fmaf(-lv, yv.w, acc.w);
                    }
                    Yf4[i2*16 + colg] = acc;
                }
            }
            __syncthreads();
        }
    }

    // final scale
    for (int idx = tid; idx < 16384; idx += 1024)
        Yf[idx] *= rd[idx >> 6];
    __syncthreads();

    // transpose-write to g_Ct[m][k]
    float* Ct = g_Ct + (size_t)b * MCON * NV;
    const int ty = tid >> 5, tx = tid & 31;
    for (int i0 = 0; i0 < 256; i0 += 32) {
        for (int j0 = 0; j0 < 64; j0 += 32) {
            tile[ty*33 + tx] = Yf[(i0 + ty)*64 + j0 + tx];
            __syncthreads();
            Ct[(size_t)(g*64 + j0 + ty)*NV + i0 + tx] = tile[tx*33 + ty];
            __syncthreads();
        }
    }
}

// ---------------------------------------------------------------------------
// gsyrk: G = Ct Ct^T. 128x128 tiles, 4x4 upper pairs (10), mirrored writes.
// 256 threads, 8x8 register micro-tile, BK=16, K=256.
// ---------------------------------------------------------------------------
__global__ void __launch_bounds__(256) gsyrk_kernel()
{
    const int pr = blockIdx.x, b = blockIdx.y, tid = threadIdx.x;
    int ti, tj;
    if      (pr < 4) { ti = 0; tj = pr;     }
    else if (pr < 7) { ti = 1; tj = pr - 3; }
    else if (pr < 9) { ti = 2; tj = pr - 5; }
    else             { ti = 3; tj = 3;      }

    __shared__ float As[16][132], Bs[16][132];
    const float* Ct = g_Ct + (size_t)b * MCON * NV;
    const int rr = tid & 127, kh = tid >> 7;     // loader: row, k-half
    const int ty = tid >> 4, tx = tid & 15;      // compute: 16x16

    float acc[8][8] = {};
    for (int k0 = 0; k0 < 256; k0 += 16) {
        {
            const float* sa = Ct + (size_t)(ti*128 + rr)*NV + k0 + kh*8;
            float4 v0 = *(const float4*)sa;
            float4 v1 = *(const float4*)(sa + 4);
            As[kh*8+0][rr] = v0.x; As[kh*8+1][rr] = v0.y;
            As[kh*8+2][rr] = v0.z; As[kh*8+3][rr] = v0.w;
            As[kh*8+4][rr] = v1.x; As[kh*8+5][rr] = v1.y;
            As[kh*8+6][rr] = v1.z; As[kh*8+7][rr] = v1.w;
            const float* sb = Ct + (size_t)(tj*128 + rr)*NV + k0 + kh*8;
            float4 w0 = *(const float4*)sb;
            float4 w1 = *(const float4*)(sb + 4);
            Bs[kh*8+0][rr] = w0.x; Bs[kh*8+1][rr] = w0.y;
            Bs[kh*8+2][rr] = w0.z; Bs[kh*8+3][rr] = w0.w;
            Bs[kh*8+4][rr] = w1.x; Bs[kh*8+5][rr] = w1.y;
            Bs[kh*8+6][rr] = w1.z; Bs[kh*8+7][rr] = w1.w;
        }
        __syncthreads();
#pragma unroll
        for (int kk = 0; kk < 16; kk++) {
            float a[8], bb[8];
            *(float4*)(a)     = *(float4*)&As[kk][ty*8];
            *(float4*)(a + 4) = *(float4*)&As[kk][ty*8 + 4];
            *(float4*)(bb)     = *(float4*)&Bs[kk][tx*8];
            *(float4*)(bb + 4) = *(float4*)&Bs[kk][tx*8 + 4];
#pragma unroll
            for (int r = 0; r < 8; r++)
#pragma unroll
                for (int c = 0; c < 8; c++)
                    acc[r][c] = fmaf(a[r], bb[c], acc[r][c]);
        }
        __syncthreads();
    }

    float* G = g_G + (size_t)b * MCON * MCON;
#pragma unroll
    for (int r = 0; r < 8; r++) {
        const int i = ti*128 + ty*8 + r;
        *(float4*)(G + (size_t)i*MCON + tj*128 + tx*8)     = *(float4*)&acc[r][0];
        *(float4*)(G + (size_t)i*MCON + tj*128 + tx*8 + 4) = *(float4*)&acc[r][4];
    }
    if (ti != tj) {
#pragma unroll
        for (int r = 0; r < 8; r++)
#pragma unroll
            for (int c = 0; c < 8; c++)
                G[(size_t)(tj*128 + tx*8 + c)*MCON + ti*128 + ty*8 + r] = acc[r][c];
    }
}

__global__ void noop_kernel() {}

// ---------------------------------------------------------------------------
// admm2: 2-CTA cluster per batch, 1024 thr, 100 iterations per launch.
// One GEMV (z~ = z0 + G w) + elementwise per iter; one cluster barrier.
// ---------------------------------------------------------------------------
__global__ void __launch_bounds__(1024, 1) __cluster_dims__(2, 1, 1)
admm2_kernel(const float* __restrict__ A, const float* __restrict__ l,
             const float* __restrict__ u, int phase)
{
    const int b = blockIdx.x >> 1, r = blockIdx.x & 1;
    const int tid = threadIdx.x;
    extern __shared__ float sh[];
    float* Gs   = sh;            // 104 rows x 516 (padded)
    float* wbuf = sh + 53664;    // 2 x 512
    float* x0_s = sh + 54688;    // 256
    // total 54944 floats = 219776 B
    float4* Gs4 = (float4*)Gs;                    // row stride 129 f4
    const float4* w4a = (const float4*)wbuf;
    const float4* w4b = (const float4*)(wbuf + 512);
    const float4* x04 = (const float4*)x0_s;

    const float RHO = 0.1f, ALPHA = 1.6f, OMA = -0.6f;
    const float4* G4g = (const float4*)(g_G + (size_t)b * MCON * MCON);
    const float4* A4g = (const float4*)(A + (size_t)b * MCON * NV);

    for (int i4 = tid; i4 < 104*128; i4 += 1024) {
        const int row = i4 >> 7, c4 = i4 & 127;
        Gs4[row*129 + c4] = G4g[(size_t)(r*256 + row)*128 + c4];
    }

    const int rowB = tid >> 2, qu = tid & 3, mg = r*256 + rowB;
    const bool own = (qu == 0);
    float* st = g_state + (size_t)b * 2048;
    float sacc = 0.f, z_r = 0.f, y_r = 0.f, l_r = 0.f, u_r = 0.f, z0_r = 0.f, w_r = 0.f;
    if (own) {
        l_r = l[b*MCON + mg]; u_r = u[b*MCON + mg];
        if (phase) { sacc = st[mg]; z_r = st[512 + mg]; y_r = st[1024 + mg]; z0_r = st[1536 + mg]; }
    }
    if (phase == 0 && tid < NV) x0_s[tid] = g_x0[b*NV + tid];
    __syncthreads();

    if (phase == 0) {
        // z0 = A x0 for own m rows
        float4 a0 = {0,0,0,0};
        const float4* Arow = A4g + (size_t)mg * 64;
#pragma unroll
        for (int t = 0; t < 16; t++)
            dot4(a0, __ldcg(Arow + qu + 4*t), x04[qu + 4*t]);
        float s = (a0.x + a0.y) + (a0.z + a0.w);
        s += __shfl_xor_sync(0xffffffffu, s, 1);
        s += __shfl_xor_sync(0xffffffffu, s, 2);
        if (own) z0_r = s;
    }

    uint32_t ra_w0 = 0, ra_w1 = 0;
    if (own) {
        const uint32_t peer = (uint32_t)(r ^ 1);
        ra_w0 = mapa_u32((uint32_t)__cvta_generic_to_shared(wbuf + mg), peer);
        ra_w1 = mapa_u32((uint32_t)__cvta_generic_to_shared(wbuf + 512 + mg), peer);
        w_r = fmaf(RHO, z_r, -y_r);
        wbuf[mg] = w_r;
        st_cluster_f32(ra_w0, w_r);
    }
    CLUSTER_ARRIVE(); CLUSTER_WAIT();

    for (int it = 0; it < 100; it++) {
        const float4* w4 = (it & 1) ? w4b : w4a;
        float4 a0 = {0,0,0,0}, a1 = {0,0,0,0};
        if (rowB < 104) {
            const float4* Grow = Gs4 + rowB*129;
#pragma unroll
            for (int t = 0; t < 32; t += 2) {
                dot4(a0, Grow[qu + 4*t],       w4[qu + 4*t]);
                dot4(a1, Grow[qu + 4*(t+1)],   w4[qu + 4*(t+1)]);
            }
        } else {
            const float4* Grow = G4g + (size_t)mg * 128;
#pragma unroll
            for (int t = 0; t < 32; t += 2) {
                dot4(a0, __ldcg(Grow + qu + 4*t),     w4[qu + 4*t]);
                dot4(a1, __ldcg(Grow + qu + 4*(t+1)), w4[qu + 4*(t+1)]);
            }
        }
        float s = (a0.x + a0.y) + (a0.z + a0.w) + (a1.x + a1.y) + (a1.z + a1.w);
        s += __shfl_xor_sync(0xffffffffu, s, 1);
        s += __shfl_xor_sync(0xffffffffu, s, 2);
        if (own) {
            sacc = fmaf(OMA, sacc, ALPHA * w_r);          // uses w of THIS iter
            float zt = z0_r + s;
            float zr = fmaf(ALPHA, zt, OMA * z_r);
            float zc = fminf(fmaxf(fmaf(y_r, 10.0f, zr), l_r), u_r);  // 1/RHO=10
            y_r = fmaf(RHO, zr - zc, y_r);
            z_r = zc;
            w_r = fmaf(RHO, z_r, -y_r);
            if (it & 1) { wbuf[mg] = w_r;       st_cluster_f32(ra_w0, w_r); }
            else        { wbuf[512 + mg] = w_r; st_cluster_f32(ra_w1, w_r); }
        }
        CLUSTER_ARRIVE(); CLUSTER_WAIT();
    }

    if (own) {
        if (phase == 0) {
            st[mg] = sacc; st[512 + mg] = z_r; st[1024 + mg] = y_r; st[1536 + mg] = z0_r;
        } else {
            st[mg] = sacc;
        }
    }
}

// ---------------------------------------------------------------------------
// finish: v = A^T sacc; solve M xh = v; out = x0 + xh. One block per batch.
// ---------------------------------------------------------------------------
__global__ void __launch_bounds__(1024) finish_kernel(const float* __restrict__ A,
                                                      float* __restrict__ out)
{
    const int b = blockIdx.x, tid = threadIdx.x;
    __shared__ float sacc_s[512];
    __shared__ float red[4096];
    __shared__ float vv[256];
    __shared__ float rds[256];
    const float* st = g_state + (size_t)b * 2048;
    const float* M = g_M + (size_t)b * NV * NV;
    const float* W = g_W + (size_t)b * NV * NV;

    if (tid < 512) sacc_s[tid] = st[tid];
    if (tid < NV) rds[tid] = 1.0f / M[(size_t)tid*NV + tid];
    __syncthreads();

    // v = A^T sacc
    const float4* A4g = (const float4*)(A + (size_t)b * MCON * NV);
    const int ms = tid >> 6, jg = tid & 63;
    float4 acc = {0,0,0,0};
    for (int m = ms; m < MCON; m += 16)
        fma4(acc, __ldcg(A4g + (size_t)m*64 + jg), sacc_s[m]);
    ((float4*)red)[ms*64 + jg] = acc;
    __syncthreads();
    if (tid < NV) {
        float v = 0.f;
#pragma unroll
        for (int s = 0; s < 16; s++) v += red[s*256 + tid];
        vv[tid] = v;
    }
    __syncthreads();

    // fwd: L y = v (unscaled accumulators)
    for (int j = 0; j < NV; j++) {
        float yj = vv[j] * rds[j];
        __syncthreads();
        if (tid < NV && tid > j)
            vv[tid] = fmaf(-M[(size_t)j*NV + tid], yj, vv[tid]);
        __syncthreads();
    }
    if (tid < NV) vv[tid] *= rds[tid];
    __syncthreads();
    // bwd: L^T x = y
    for (int j = NV - 1; j >= 0; j--) {
        float xj = vv[j] * rds[j];
        __syncthreads();
        if (tid < j)
            vv[tid] = fmaf(-W[(size_t)j*NV + tid], xj, vv[tid]);
        __syncthreads();
    }
    if (tid < NV)
        out[b*NV + tid] = g_x0[b*NV + tid] + vv[tid] * rds[tid];
}

// ---------------------------------------------------------------------------
extern "C" void kernel_launch(void* const* d_in, const int* in_sizes, int n_in,
                              void* d_out, int out_size)
{
    const float* P = (const float*)d_in[0];
    const float* q = (const float*)d_in[1];
    const float* A = (const float*)d_in[2];
    const float* l = (const float*)d_in[3];
    const float* u = (const float*)d_in[4];
    float* out = (float*)d_out;

    const int CHOL_SMEM   = 192 * 256 * 4;   // 196608
    const int CSOLVE_SMEM = 28096 * 4;       // 112384
    const int ADMM_SMEM   = 54944 * 4;       // 219776
    cudaFuncSetAttribute(setup2_kernel, cudaFuncAttributeMaxDynamicSharedMemorySize, CHOL_SMEM);
    cudaFuncSetAttribute(csolve_kernel, cudaFuncAttributeMaxDynamicSharedMemorySize, CSOLVE_SMEM);
    cudaFuncSetAttribute(admm2_kernel,  cudaFuncAttributeMaxDynamicSharedMemorySize, ADMM_SMEM);

    setup1_kernel<<<dim3(10, NBAT), 256>>>(A, P);
    setup2_kernel<<<NBAT, 1024, CHOL_SMEM>>>(q);
    csolve_kernel<<<dim3(8, NBAT), 1024, CSOLVE_SMEM>>>(A);
    gsyrk_kernel<<<dim3(10, NBAT), 256>>>();
    admm2_kernel<<<2 * NBAT, 1024, ADMM_SMEM>>>(A, l, u, 0);
    noop_kernel<<<1, 32>>>();
    admm2_kernel<<<2 * NBAT, 1024, ADMM_SMEM>>>(A, l, u, 1);
    finish_kernel<<<NBAT, 1024>>>(A, out);
}

// round 14
// speedup vs baseline: 1.0871x; 1.0758x over previous
#include <cuda_runtime.h>
#include <cstdint>

// Batched OSQP ADMM: B=64, n=256, m=512, 200 iterations.
// G = A Minv A^T; loop: z~ = z0 + G w (one GEMV + one cluster barrier);
// sacc accumulates alpha-weighted w's; out = Minv(A^T sacc - q) at the end.
// setup1: syrk  M = rho*A'A + diag(P)+sigma
// setup2: BLOCKED Cholesky (32-col slabs, lazy GEMM updates) + W = L^T
// csolve: C = L^{-1} [A^T | q]  (9 column-blocks; block 8 yields cq)
// gsyrk:  G = Ct Ct^T (10 tile-pair blocks) + z0 = -Ct cq (block 10)
// admm2:  2-CTA cluster/batch, 1024 thr, 100 iters/launch, 100 G-rows in
//         SMEM at conflict-free stride 132 f4, rest L2-streamed (ldcg).
// finish: v = A^T sacc - q; solve M x = v; out = x.

#define NBAT 64
#define NV   256
#define MCON 512

__device__ float g_M [(size_t)NBAT*NV*NV];      // M, then L (col-major lower)
__device__ float g_W [(size_t)NBAT*NV*NV];      // L row-major
__device__ float g_Ct[(size_t)NBAT*MCON*NV];    // Ct[m][k] = (L^{-1}A^T)[k][m]
__device__ float g_G [(size_t)NBAT*MCON*MCON];  // G = A Minv A^T, row-major
__device__ float g_cq[(size_t)NBAT*NV];         // L^{-1} q
__device__ float g_z0[(size_t)NBAT*MCON];       // -Ct cq = A x0
__device__ float g_state[(size_t)NBAT*2048];    // sacc 512 | z 512 | y 512 | pad

__device__ __forceinline__ void fma4(float4& a, const float4 v, const float s) {
    a.x = fmaf(v.x, s, a.x); a.y = fmaf(v.y, s, a.y);
    a.z = fmaf(v.z, s, a.z); a.w = fmaf(v.w, s, a.w);
}
__device__ __forceinline__ void dot4(float4& a, const float4 v, const float4 s) {
    a.x = fmaf(v.x, s.x, a.x); a.y = fmaf(v.y, s.y, a.y);
    a.z = fmaf(v.z, s.z, a.z); a.w = fmaf(v.w, s.w, a.w);
}
__device__ __forceinline__ uint32_t mapa_u32(uint32_t laddr, uint32_t rank) {
    uint32_t ra;
    asm("mapa.shared::cluster.u32 %0, %1, %2;" : "=r"(ra) : "r"(laddr), "r"(rank));
    return ra;
}
__device__ __forceinline__ void st_cluster_f32(uint32_t addr, float v) {
    asm volatile("st.shared::cluster.f32 [%0], %1;" :: "r"(addr), "f"(v) : "memory");
}
#define CLUSTER_ARRIVE() asm volatile("barrier.cluster.arrive.aligned;" ::: "memory")
#define CLUSTER_WAIT()   asm volatile("barrier.cluster.wait.aligned;"   ::: "memory")

// ---------------------------------------------------------------------------
// setup1: syrk 64x64 tile pairs, 10 blocks per batch.
// ---------------------------------------------------------------------------
__global__ void __launch_bounds__(256) setup1_kernel(const float* __restrict__ A,
                                                     const float* __restrict__ P)
{
    const int pr = blockIdx.x, b = blockIdx.y;
    const int tid = threadIdx.x;
    int ti, tj;
    if      (pr < 4) { ti = 0; tj = pr;     }
    else if (pr < 7) { ti = 1; tj = pr - 3; }
    else if (pr < 9) { ti = 2; tj = pr - 5; }
    else             { ti = 3; tj = 3;      }

    __shared__ float As[16 * 64], Bs[16 * 64];
    const float* Ab = A + (size_t)b * MCON * NV;
    const int lr = tid >> 4, lc = tid & 15;

    float acc[4][4] = {};
    for (int k0 = 0; k0 < MCON; k0 += 16) {
        *(float4*)(As + lr*64 + lc*4) = *(const float4*)(Ab + (size_t)(k0+lr)*NV + ti*64 + lc*4);
        *(float4*)(Bs + lr*64 + lc*4) = *(const float4*)(Ab + (size_t)(k0+lr)*NV + tj*64 + lc*4);
        __syncthreads();
#pragma unroll
        for (int kk = 0; kk < 16; kk++) {
            float4 a4 = *(float4*)(As + kk*64 + lr*4);
            float4 b4 = *(float4*)(Bs + kk*64 + lc*4);
            float av[4] = {a4.x, a4.y, a4.z, a4.w};
            float bv[4] = {b4.x, b4.y, b4.z, b4.w};
#pragma unroll
            for (int r = 0; r < 4; r++)
#pragma unroll
                for (int s = 0; s < 4; s++)
                    acc[r][s] = fmaf(av[r], bv[s], acc[r][s]);
        }
        __syncthreads();
    }

    float* Mb = g_M + (size_t)b * NV * NV;
    const float RHO = 0.1f, SIGMA = 1e-6f;
#pragma unroll
    for (int r = 0; r < 4; r++)
#pragma unroll
        for (int s = 0; s < 4; s++) {
            int i = ti*64 + lr*4 + r;
            int j = tj*64 + lc*4 + s;
            float v = RHO * acc[r][s];
            if (i == j) v += P[b*NV + i] + SIGMA;
            Mb[(size_t)i*NV + j] = v;
            if (ti != tj) Mb[(size_t)j*NV + i] = v;
        }
}

// ---------------------------------------------------------------------------
// setup2: BLOCKED left-looking Cholesky. L stored col-major in g_M rows
// (g_M row j = column j of L, rows >= j valid). Then W = L row-major.
// Per 32-col panel: load slab -> lazy GEMM update from prior panels ->
// serial factor (outer-product form, 1 sync/step) -> scale + write back.
// ---------------------------------------------------------------------------
__global__ void __launch_bounds__(1024) setup2_kernel()
{
    const int b = blockIdx.x, tid = threadIdx.x;
    float* M = g_M + (size_t)b * NV * NV;
    extern __shared__ float sm2[];
    float* S   = sm2;           // 32 cols x 260 (col-major slab)
    float* Lk  = sm2 + 8320;    // 16 x 260
    float* rdv = sm2 + 12480;   // 32
    __shared__ float st[32][33];

    const int jj_u = tid & 31, rg = tid >> 5;     // lazy-update map
    const int i2r  = tid & 255, cs = tid >> 8;    // serial map

    for (int p = 0; p < 8; p++) {
        const int P0 = 32 * p, R = NV - P0;
        // load slab: col jj = g_M row (P0+jj), entries [P0, 256)
        for (int e = tid; e < 32 * R; e += 1024) {
            const int jj = e / R, i2 = e - jj * R;
            S[jj*260 + i2] = M[(size_t)(P0 + jj)*NV + P0 + i2];
        }
        __syncthreads();

        // lazy update: S[jj][i2] -= sum_{k<P0} L[P0+i2][k] * L[P0+jj][k]
        float acc[8] = {};
        for (int k0 = 0; k0 < P0; k0 += 16) {
            for (int e = tid; e < 16 * R; e += 1024) {
                const int kk = e / R, i2 = e - kk * R;
                Lk[kk*260 + i2] = M[(size_t)(k0 + kk)*NV + P0 + i2];
            }
            __syncthreads();
#pragma unroll 4
            for (int kk = 0; kk < 16; kk++) {
                const float bv = Lk[kk*260 + jj_u];
                const float* ar = Lk + kk*260 + rg*8;
#pragma unroll
                for (int t = 0; t < 8; t++)
                    acc[t] = fmaf(ar[t], bv, acc[t]);
            }
            __syncthreads();
        }
        if (P0 > 0) {
#pragma unroll
            for (int t = 0; t < 8; t++) {
                const int i2 = rg*8 + t;
                if (i2 < R) S[jj_u*260 + i2] -= acc[t];
            }
        }
        __syncthreads();

        // serial factor: one sync per step (outer-product updates)
        for (int jj = 0; jj < 32; jj++) {
            const float d = S[jj*260 + jj];
            const float invd = 1.0f / d;
            if (tid == 0) rdv[jj] = rsqrtf(d);
            if (i2r < R) {
                const float v = S[jj*260 + i2r];
                for (int jj2 = jj + 1 + cs; jj2 < 32; jj2 += 4) {
                    const float f = S[jj*260 + jj2] * invd;
                    S[jj2*260 + i2r] = fmaf(-f, v, S[jj2*260 + i2r]);
                }
            }
            __syncthreads();
        }

        // scale + write back
        for (int e = tid; e < 32 * R; e += 1024) {
            const int jj = e / R, i2 = e - jj * R;
            M[(size_t)(P0 + jj)*NV + P0 + i2] = S[jj*260 + i2] * rdv[jj];
        }
        __syncthreads();
    }

    // W = L row-major via conflict-free tile transposes
    float* W = g_W + (size_t)b * NV * NV;
    const int ty = tid >> 5, tx = tid & 31;
    for (int k0 = 0; k0 < NV; k0 += 32) {
        for (int i0 = 0; i0 < NV; i0 += 32) {
            st[ty][tx] = M[(size_t)(k0 + ty)*NV + i0 + tx];
            __syncthreads();
            W[(size_t)(i0 + ty)*NV + k0 + tx] = st[tx][ty];
            __syncthreads();
        }
    }
}

// ---------------------------------------------------------------------------
// csolve: block (g, b), g<8: 64 columns of C = L^{-1} A^T -> g_Ct (transposed).
// g==8: RHS col 0 = q, rest 0 -> cq = L^{-1} q -> g_cq.
// Blocked forward trsm: 32-row serial panels + register-tiled updates.
// ---------------------------------------------------------------------------
__global__ void __launch_bounds__(1024) csolve_kernel(const float* __restrict__ A,
                                                      const float* __restrict__ qv)
{
    const int g = blockIdx.x, b = blockIdx.y, tid = threadIdx.x;
    extern __shared__ float sm[];
    float* Yf   = sm;                 // 16384 (256 x 64)
    float* Lg   = sm + 16384;         // 7168  (32 x 224)
    float* Ys   = sm + 23552;         // 2176  (32 x 68)
    float* Ld   = sm + 25728;         // 1056  (32 x 33)
    float* rd   = sm + 26784;         // 256
    float* tile = sm + 27040;         // 1056

    const float* M  = g_M + (size_t)b * NV * NV;
    const float* Ab = A + (size_t)b * MCON * NV;
    float2* Y2 = (float2*)Yf;
    float4* Yf4 = (float4*)Yf;
    const float4* Ys4 = (const float4*)Ys;

    if (tid < NV) rd[tid] = 1.0f / M[(size_t)tid*NV + tid];
    if (g < 8) {
        for (int idx = tid; idx < 16384; idx += 1024) {
            const int i = idx >> 6, jj = idx & 63;
            Yf[idx] = Ab[(size_t)(g*64 + jj)*NV + i];
        }
    } else {
        for (int idx = tid; idx < 16384; idx += 1024) {
            const int i = idx >> 6, jj = idx & 63;
            Yf[idx] = (jj == 0) ? qv[b*NV + i] : 0.0f;
        }
    }
    __syncthreads();

    const int qd = tid >> 5, c2 = tid & 31;
    const int rowg = tid >> 4, colg = tid & 15;

    for (int p = 0; p < 8; p++) {
        const int P0 = 32 * p;
        {
            const int j = tid >> 5, i2 = tid & 31;
            Ld[j*33 + i2] = M[(size_t)(P0 + j)*NV + P0 + i2];
        }
        __syncthreads();

        for (int li = 0; li < 32; li++) {
            const int i = P0 + li;
            float2 yv = Y2[i*32 + c2];
            const float sc = rd[i];
            yv.x *= sc; yv.y *= sc;
            if (qd > li) {
                const float lv = Ld[li*33 + qd];
                float2 t = Y2[(P0 + qd)*32 + c2];
                t.x = fmaf(-lv, yv.x, t.x);
                t.y = fmaf(-lv, yv.y, t.y);
                Y2[(P0 + qd)*32 + c2] = t;
            }
            __syncthreads();
        }

        if (p < 7) {
            const int R = 224 - 32*p;
            for (int e = tid; e < 2048; e += 1024) {
                const int k = e >> 6, j = e & 63;
                Ys[k*68 + j] = Yf[(P0 + k)*64 + j] * rd[P0 + k];
            }
            for (int e = tid; e < 32*R; e += 1024) {
                const int k = e / R, ir = e - k*R;
                Lg[k*224 + ir] = M[(size_t)(P0 + k)*NV + P0 + 32 + ir];
            }
            __syncthreads();

#pragma unroll
            for (int rrr = 0; rrr < 4; rrr++) {
                const int i2r2 = rowg + 64*rrr;
                if (i2r2 < R) {
                    const int i2 = P0 + 32 + i2r2;
                    float4 a = Yf4[i2*16 + colg];
#pragma unroll
                    for (int k = 0; k < 32; k++) {
                        const float lv = Lg[k*224 + i2r2];
                        const float4 yv = Ys4[k*17 + colg];
                        a.x = fmaf(-lv, yv.x, a.x);
                        a.y = fmaf(-lv, yv.y, a.y);
                        a.z = fmaf(-lv, yv.z, a.z);
                        a.w = fmaf(-lv, yv.w, a.w);
                    }
                    Yf4[i2*16 + colg] = a;
                }
            }
            __syncthreads();
        }
    }

    for (int idx = tid; idx < 16384; idx += 1024)
        Yf[idx] *= rd[idx >> 6];
    __syncthreads();

    if (g < 8) {
        float* Ct = g_Ct + (size_t)b * MCON * NV;
        const int ty = tid >> 5, tx = tid & 31;
        for (int i0 = 0; i0 < 256; i0 += 32) {
            for (int j0 = 0; j0 < 64; j0 += 32) {
                tile[ty*33 + tx] = Yf[(i0 + ty)*64 + j0 + tx];
                __syncthreads();
                Ct[(size_t)(g*64 + j0 + ty)*NV + i0 + tx] = tile[tx*33 + ty];
                __syncthreads();
            }
        }
    } else {
        if (tid < NV) g_cq[b*NV + tid] = Yf[tid*64 + 0];
    }
}

// ---------------------------------------------------------------------------
// gsyrk: blocks 0..9: G = Ct Ct^T (128x128 tile pairs, mirrored).
//        block 10: z0 = -Ct cq.
// ---------------------------------------------------------------------------
__global__ void __launch_bounds__(256) gsyrk_kernel()
{
    const int pr = blockIdx.x, b = blockIdx.y, tid = threadIdx.x;
    const float* Ct = g_Ct + (size_t)b * MCON * NV;

    if (pr == 10) {
        __shared__ float cqs[256];
        cqs[tid] = g_cq[b*NV + tid];
        __syncthreads();
        const float4* Ct4 = (const float4*)Ct;
        const float4* cq4 = (const float4*)cqs;
        for (int m = tid; m < MCON; m += 256) {
            float4 a = {0.f, 0.f, 0.f, 0.f};
#pragma unroll 8
            for (int k4 = 0; k4 < 64; k4++)
                dot4(a, Ct4[(size_t)m*64 + k4], cq4[k4]);
            g_z0[b*MCON + m] = -((a.x + a.y) + (a.z + a.w));
        }
        return;
    }

    int ti, tj;
    if      (pr < 4) { ti = 0; tj = pr;     }
    else if (pr < 7) { ti = 1; tj = pr - 3; }
    else if (pr < 9) { ti = 2; tj = pr - 5; }
    else             { ti = 3; tj = 3;      }

    __shared__ float As[16][132], Bs[16][132];
    const int rr = tid & 127, kh = tid >> 7;
    const int ty = tid >> 4, tx = tid & 15;

    float acc[8][8] = {};
    for (int k0 = 0; k0 < 256; k0 += 16) {
        {
            const float* sa = Ct + (size_t)(ti*128 + rr)*NV + k0 + kh*8;
            float4 v0 = *(const float4*)sa;
            float4 v1 = *(const float4*)(sa + 4);
            As[kh*8+0][rr] = v0.x; As[kh*8+1][rr] = v0.y;
            As[kh*8+2][rr] = v0.z; As[kh*8+3][rr] = v0.w;
            As[kh*8+4][rr] = v1.x; As[kh*8+5][rr] = v1.y;
            As[kh*8+6][rr] = v1.z; As[kh*8+7][rr] = v1.w;
            const float* sb = Ct + (size_t)(tj*128 + rr)*NV + k0 + kh*8;
            float4 w0 = *(const float4*)sb;
            float4 w1 = *(const float4*)(sb + 4);
            Bs[kh*8+0][rr] = w0.x; Bs[kh*8+1][rr] = w0.y;
            Bs[kh*8+2][rr] = w0.z; Bs[kh*8+3][rr] = w0.w;
            Bs[kh*8+4][rr] = w1.x; Bs[kh*8+5][rr] = w1.y;
            Bs[kh*8+6][rr] = w1.z; Bs[kh*8+7][rr] = w1.w;
        }
        __syncthreads();
#pragma unroll
        for (int kk = 0; kk < 16; kk++) {
            float a[8], bb[8];
            *(float4*)(a)      = *(float4*)&As[kk][ty*8];
            *(float4*)(a + 4)  = *(float4*)&As[kk][ty*8 + 4];
            *(float4*)(bb)     = *(float4*)&Bs[kk][tx*8];
            *(float4*)(bb + 4) = *(float4*)&Bs[kk][tx*8 + 4];
#pragma unroll
            for (int r = 0; r < 8; r++)
#pragma unroll
                for (int c = 0; c < 8; c++)
                    acc[r][c] = fmaf(a[r], bb[c], acc[r][c]);
        }
        __syncthreads();
    }

    float* G = g_G + (size_t)b * MCON * MCON;
#pragma unroll
    for (int r = 0; r < 8; r++) {
        const int i = ti*128 + ty*8 + r;
        *(float4*)(G + (size_t)i*MCON + tj*128 + tx*8)     = *(float4*)&acc[r][0];
        *(float4*)(G + (size_t)i*MCON + tj*128 + tx*8 + 4) = *(float4*)&acc[r][4];
    }
    if (ti != tj) {
#pragma unroll
        for (int r = 0; r < 8; r++)
#pragma unroll
            for (int c = 0; c < 8; c++)
                G[(size_t)(tj*128 + tx*8 + c)*MCON + ti*128 + ty*8 + r] = acc[r][c];
    }
}

__global__ void noop_kernel() {}

// ---------------------------------------------------------------------------
// admm2: 2-CTA cluster per batch, 1024 thr, 100 iterations per launch.
// ---------------------------------------------------------------------------
__global__ void __launch_bounds__(1024, 1) __cluster_dims__(2, 1, 1)
admm2_kernel(const float* __restrict__ l, const float* __restrict__ u, int phase)
{
    const int b = blockIdx.x >> 1, r = blockIdx.x & 1;
    const int tid = threadIdx.x;
    extern __shared__ float sh[];
    float* Gs   = sh;            // 100 rows x 132 f4 (conflict-free)
    float* wbuf = sh + 52800;    // 2 x 512
    // total 53824 floats = 215296 B
    float4* Gs4 = (float4*)Gs;
    const float4* w4a = (const float4*)wbuf;
    const float4* w4b = (const float4*)(wbuf + 512);

    const float RHO = 0.1f, ALPHA = 1.6f, OMA = -0.6f;
    const float4* G4g = (const float4*)(g_G + (size_t)b * MCON * MCON);

    for (int i4 = tid; i4 < 100*128; i4 += 1024) {
        const int row = i4 >> 7, c4 = i4 & 127;
        Gs4[row*132 + c4] = G4g[(size_t)(r*256 + row)*128 + c4];
    }

    const int rowB = tid >> 2, qu = tid & 3, mg = r*256 + rowB;
    const bool own = (qu == 0);
    float* st = g_state + (size_t)b * 2048;
    float sacc = 0.f, z_r = 0.f, y_r = 0.f, l_r = 0.f, u_r = 0.f, z0_r = 0.f, w_r = 0.f;
    uint32_t ra_w0 = 0, ra_w1 = 0;
    if (own) {
        l_r = l[b*MCON + mg]; u_r = u[b*MCON + mg];
        z0_r = g_z0[b*MCON + mg];
        if (phase) { sacc = st[mg]; z_r = st[512 + mg]; y_r = st[1024 + mg]; }
        const uint32_t peer = (uint32_t)(r ^ 1);
        ra_w0 = mapa_u32((uint32_t)__cvta_generic_to_shared(wbuf + mg), peer);
        ra_w1 = mapa_u32((uint32_t)__cvta_generic_to_shared(wbuf + 512 + mg), peer);
        w_r = fmaf(RHO, z_r, -y_r);
        wbuf[mg] = w_r;
        st_cluster_f32(ra_w0, w_r);
    }
    __syncthreads();
    CLUSTER_ARRIVE(); CLUSTER_WAIT();

    for (int it = 0; it < 100; it++) {
        const float4* w4 = (it & 1) ? w4b : w4a;
        float4 a0 = {0,0,0,0}, a1 = {0,0,0,0};
        if (rowB < 100) {
            const float4* Grow = Gs4 + rowB*132;
#pragma unroll
            for (int t = 0; t < 32; t += 2) {
                dot4(a0, Grow[qu + 4*t],     w4[qu + 4*t]);
                dot4(a1, Grow[qu + 4*(t+1)], w4[qu + 4*(t+1)]);
            }
        } else {
            const float4* Grow = G4g + (size_t)mg * 128;
#pragma unroll
            for (int t = 0; t < 32; t += 2) {
                dot4(a0, __ldcg(Grow + qu + 4*t),     w4[qu + 4*t]);
                dot4(a1, __ldcg(Grow + qu + 4*(t+1)), w4[qu + 4*(t+1)]);
            }
        }
        float s = (a0.x + a0.y) + (a0.z + a0.w) + (a1.x + a1.y) + (a1.z + a1.w);
        s += __shfl_xor_sync(0xffffffffu, s, 1);
        s += __shfl_xor_sync(0xffffffffu, s, 2);
        if (own) {
            sacc = fmaf(OMA, sacc, ALPHA * w_r);
            float zt = z0_r + s;
            float zr = fmaf(ALPHA, zt, OMA * z_r);
            float zc = fminf(fmaxf(fmaf(y_r, 10.0f, zr), l_r), u_r);  // 1/RHO=10
            y_r = fmaf(RHO, zr - zc, y_r);
            z_r = zc;
            w_r = fmaf(RHO, z_r, -y_r);
            if (it & 1) { wbuf[mg] = w_r;       st_cluster_f32(ra_w0, w_r); }
            else        { wbuf[512 + mg] = w_r; st_cluster_f32(ra_w1, w_r); }
        }
        CLUSTER_ARRIVE(); CLUSTER_WAIT();
    }

    if (own) {
        if (phase == 0) {
            st[mg] = sacc; st[512 + mg] = z_r; st[1024 + mg] = y_r;
        } else {
            st[mg] = sacc;
        }
    }
}

// ---------------------------------------------------------------------------
// finish: v = A^T sacc - q; solve M x = v; out = x. One block per batch.
// ---------------------------------------------------------------------------
__global__ void __launch_bounds__(1024) finish_kernel(const float* __restrict__ A,
                                                      const float* __restrict__ qv,
                                                      float* __restrict__ out)
{
    const int b = blockIdx.x, tid = threadIdx.x;
    __shared__ float sacc_s[512];
    __shared__ float red[4096];
    __shared__ float vv[256];
    __shared__ float rds[256];
    const float* st = g_state + (size_t)b * 2048;
    const float* M = g_M + (size_t)b * NV * NV;
    const float* W = g_W + (size_t)b * NV * NV;

    if (tid < 512) sacc_s[tid] = st[tid];
    if (tid < NV) rds[tid] = 1.0f / M[(size_t)tid*NV + tid];
    __syncthreads();

    const float4* A4g = (const float4*)(A + (size_t)b * MCON * NV);
    const int ms = tid >> 6, jg = tid & 63;
    float4 acc = {0,0,0,0};
    for (int m = ms; m < MCON; m += 16)
        fma4(acc, __ldcg(A4g + (size_t)m*64 + jg), sacc_s[m]);
    ((float4*)red)[ms*64 + jg] = acc;
    __syncthreads();
    if (tid < NV) {
        float v = -qv[b*NV + tid];
#pragma unroll
        for (int s = 0; s < 16; s++) v += red[s*256 + tid];
        vv[tid] = v;
    }
    __syncthreads();

    for (int j = 0; j < NV; j++) {
        float yj = vv[j] * rds[j];
        __syncthreads();
        if (tid < NV && tid > j)
            vv[tid] = fmaf(-M[(size_t)j*NV + tid], yj, vv[tid]);
        __syncthreads();
    }
    if (tid < NV) vv[tid] *= rds[tid];
    __syncthreads();
    for (int j = NV - 1; j >= 0; j--) {
        float xj = vv[j] * rds[j];
        __syncthreads();
        if (tid < j)
            vv[tid] = fmaf(-W[(size_t)j*NV + tid], xj, vv[tid]);
        __syncthreads();
    }
    if (tid < NV)
        out[b*NV + tid] = vv[tid] * rds[tid];
}

// ---------------------------------------------------------------------------
extern "C" void kernel_launch(void* const* d_in, const int* in_sizes, int n_in,
                              void* d_out, int out_size)
{
    const float* P = (const float*)d_in[0];
    const float* q = (const float*)d_in[1];
    const float* A = (const float*)d_in[2];
    const float* l = (const float*)d_in[3];
    const float* u = (const float*)d_in[4];
    float* out = (float*)d_out;

    const int CHOL_SMEM   = 12512 * 4;       // 50048
    const int CSOLVE_SMEM = 28096 * 4;       // 112384
    const int ADMM_SMEM   = 53824 * 4;       // 215296
    cudaFuncSetAttribute(setup2_kernel, cudaFuncAttributeMaxDynamicSharedMemorySize, CHOL_SMEM);
    cudaFuncSetAttribute(csolve_kernel, cudaFuncAttributeMaxDynamicSharedMemorySize, CSOLVE_SMEM);
    cudaFuncSetAttribute(admm2_kernel,  cudaFuncAttributeMaxDynamicSharedMemorySize, ADMM_SMEM);

    setup1_kernel<<<dim3(10, NBAT), 256>>>(A, P);
    setup2_kernel<<<NBAT, 1024, CHOL_SMEM>>>();
    csolve_kernel<<<dim3(9, NBAT), 1024, CSOLVE_SMEM>>>(A, q);
    gsyrk_kernel<<<dim3(11, NBAT), 256>>>();
    admm2_kernel<<<2 * NBAT, 1024, ADMM_SMEM>>>(l, u, 0);
    noop_kernel<<<1, 32>>>();
    admm2_kernel<<<2 * NBAT, 1024, ADMM_SMEM>>>(l, u, 1);
    finish_kernel<<<NBAT, 1024>>>(A, q, out);
}

// round 15
// speedup vs baseline: 1.1802x; 1.0856x over previous
#include <cuda_runtime.h>
#include <cstdint>

// Batched OSQP ADMM: B=64, n=256, m=512, 200 iterations.
// Rank-256 form: C = L^{-1} A^T (256x512). G w = C^T (C w) done as
// per-CTA partial products over own m-columns (Ct rows), so each CTA only
// ever touches its own 256 KB of C -> 196 rows SMEM-resident, 60 L2-streamed.
// One 256-float DSMEM exchange + one cluster barrier per iteration.
// setup1: syrk  M = rho*A'A + diag(P)+sigma
// setup2: BLOCKED Cholesky (32-col slabs) + W = L^T
// csolve: Ct = (L^{-1} [A^T | q])^T  (block 8 yields cq)
// z0:     z0 = -Ct cq
// admm3:  2-CTA cluster/batch, 1024 thr, 100 iters/launch
// finish: v = A^T sacc - q; solve M x = v; out = x.

#define NBAT 64
#define NV   256
#define MCON 512

__device__ float g_M [(size_t)NBAT*NV*NV];      // M, then L (col-major lower)
__device__ float g_W [(size_t)NBAT*NV*NV];      // L row-major
__device__ float g_Ct[(size_t)NBAT*MCON*NV];    // Ct[m][k] = (L^{-1}A^T)[k][m]
__device__ float g_cq[(size_t)NBAT*NV];         // L^{-1} q
__device__ float g_z0[(size_t)NBAT*MCON];       // -Ct cq = A x0
__device__ float g_state[(size_t)NBAT*2048];    // sacc 512 | z 512 | y 512 | pad

__device__ __forceinline__ void fma4(float4& a, const float4 v, const float s) {
    a.x = fmaf(v.x, s, a.x); a.y = fmaf(v.y, s, a.y);
    a.z = fmaf(v.z, s, a.z); a.w = fmaf(v.w, s, a.w);
}
__device__ __forceinline__ void dot4(float4& a, const float4 v, const float4 s) {
    a.x = fmaf(v.x, s.x, a.x); a.y = fmaf(v.y, s.y, a.y);
    a.z = fmaf(v.z, s.z, a.z); a.w = fmaf(v.w, s.w, a.w);
}
__device__ __forceinline__ uint32_t mapa_u32(uint32_t laddr, uint32_t rank) {
    uint32_t ra;
    asm("mapa.shared::cluster.u32 %0, %1, %2;" : "=r"(ra) : "r"(laddr), "r"(rank));
    return ra;
}
__device__ __forceinline__ void st_cluster_f32(uint32_t addr, float v) {
    asm volatile("st.shared::cluster.f32 [%0], %1;" :: "r"(addr), "f"(v) : "memory");
}
#define CLUSTER_ARRIVE() asm volatile("barrier.cluster.arrive.aligned;" ::: "memory")
#define CLUSTER_WAIT()   asm volatile("barrier.cluster.wait.aligned;"   ::: "memory")

// ---------------------------------------------------------------------------
// setup1: syrk 64x64 tile pairs, 10 blocks per batch.
// ---------------------------------------------------------------------------
__global__ void __launch_bounds__(256) setup1_kernel(const float* __restrict__ A,
                                                     const float* __restrict__ P)
{
    const int pr = blockIdx.x, b = blockIdx.y;
    const int tid = threadIdx.x;
    int ti, tj;
    if      (pr < 4) { ti = 0; tj = pr;     }
    else if (pr < 7) { ti = 1; tj = pr - 3; }
    else if (pr < 9) { ti = 2; tj = pr - 5; }
    else             { ti = 3; tj = 3;      }

    __shared__ float As[16 * 64], Bs[16 * 64];
    const float* Ab = A + (size_t)b * MCON * NV;
    const int lr = tid >> 4, lc = tid & 15;

    float acc[4][4] = {};
    for (int k0 = 0; k0 < MCON; k0 += 16) {
        *(float4*)(As + lr*64 + lc*4) = *(const float4*)(Ab + (size_t)(k0+lr)*NV + ti*64 + lc*4);
        *(float4*)(Bs + lr*64 + lc*4) = *(const float4*)(Ab + (size_t)(k0+lr)*NV + tj*64 + lc*4);
        __syncthreads();
#pragma unroll
        for (int kk = 0; kk < 16; kk++) {
            float4 a4 = *(float4*)(As + kk*64 + lr*4);
            float4 b4 = *(float4*)(Bs + kk*64 + lc*4);
            float av[4] = {a4.x, a4.y, a4.z, a4.w};
            float bv[4] = {b4.x, b4.y, b4.z, b4.w};
#pragma unroll
            for (int r = 0; r < 4; r++)
#pragma unroll
                for (int s = 0; s < 4; s++)
                    acc[r][s] = fmaf(av[r], bv[s], acc[r][s]);
        }
        __syncthreads();
    }

    float* Mb = g_M + (size_t)b * NV * NV;
    const float RHO = 0.1f, SIGMA = 1e-6f;
#pragma unroll
    for (int r = 0; r < 4; r++)
#pragma unroll
        for (int s = 0; s < 4; s++) {
            int i = ti*64 + lr*4 + r;
            int j = tj*64 + lc*4 + s;
            float v = RHO * acc[r][s];
            if (i == j) v += P[b*NV + i] + SIGMA;
            Mb[(size_t)i*NV + j] = v;
            if (ti != tj) Mb[(size_t)j*NV + i] = v;
        }
}

// ---------------------------------------------------------------------------
// setup2: BLOCKED left-looking Cholesky + W = L row-major.
// ---------------------------------------------------------------------------
__global__ void __launch_bounds__(1024) setup2_kernel()
{
    const int b = blockIdx.x, tid = threadIdx.x;
    float* M = g_M + (size_t)b * NV * NV;
    extern __shared__ float sm2[];
    float* S   = sm2;           // 32 cols x 260
    float* Lk  = sm2 + 8320;    // 16 x 260
    float* rdv = sm2 + 12480;   // 32
    __shared__ float st[32][33];

    const int jj_u = tid & 31, rg = tid >> 5;
    const int i2r  = tid & 255, cs = tid >> 8;

    for (int p = 0; p < 8; p++) {
        const int P0 = 32 * p, R = NV - P0;
        for (int e = tid; e < 32 * R; e += 1024) {
            const int jj = e / R, i2 = e - jj * R;
            S[jj*260 + i2] = M[(size_t)(P0 + jj)*NV + P0 + i2];
        }
        __syncthreads();

        float acc[8] = {};
        for (int k0 = 0; k0 < P0; k0 += 16) {
            for (int e = tid; e < 16 * R; e += 1024) {
                const int kk = e / R, i2 = e - kk * R;
                Lk[kk*260 + i2] = M[(size_t)(k0 + kk)*NV + P0 + i2];
            }
            __syncthreads();
#pragma unroll 4
            for (int kk = 0; kk < 16; kk++) {
                const float bv = Lk[kk*260 + jj_u];
                const float* ar = Lk + kk*260 + rg*8;
#pragma unroll
                for (int t = 0; t < 8; t++)
                    acc[t] = fmaf(ar[t], bv, acc[t]);
            }
            __syncthreads();
        }
        if (P0 > 0) {
#pragma unroll
            for (int t = 0; t < 8; t++) {
                const int i2 = rg*8 + t;
                if (i2 < R) S[jj_u*260 + i2] -= acc[t];
            }
        }
        __syncthreads();

        for (int jj = 0; jj < 32; jj++) {
            const float d = S[jj*260 + jj];
            const float invd = 1.0f / d;
            if (tid == 0) rdv[jj] = rsqrtf(d);
            if (i2r < R) {
                const float v = S[jj*260 + i2r];
                for (int jj2 = jj + 1 + cs; jj2 < 32; jj2 += 4) {
                    const float f = S[jj*260 + jj2] * invd;
                    S[jj2*260 + i2r] = fmaf(-f, v, S[jj2*260 + i2r]);
                }
            }
            __syncthreads();
        }

        for (int e = tid; e < 32 * R; e += 1024) {
            const int jj = e / R, i2 = e - jj * R;
            M[(size_t)(P0 + jj)*NV + P0 + i2] = S[jj*260 + i2] * rdv[jj];
        }
        __syncthreads();
    }

    float* W = g_W + (size_t)b * NV * NV;
    const int ty = tid >> 5, tx = tid & 31;
    for (int k0 = 0; k0 < NV; k0 += 32) {
        for (int i0 = 0; i0 < NV; i0 += 32) {
            st[ty][tx] = M[(size_t)(k0 + ty)*NV + i0 + tx];
            __syncthreads();
            W[(size_t)(i0 + ty)*NV + k0 + tx] = st[tx][ty];
            __syncthreads();
        }
    }
}

// ---------------------------------------------------------------------------
// csolve: block (g, b), g<8: 64 columns of C = L^{-1} A^T -> g_Ct (transposed).
// g==8: cq = L^{-1} q. Blocked forward trsm.
// ---------------------------------------------------------------------------
__global__ void __launch_bounds__(1024) csolve_kernel(const float* __restrict__ A,
                                                      const float* __restrict__ qv)
{
    const int g = blockIdx.x, b = blockIdx.y, tid = threadIdx.x;
    extern __shared__ float sm[];
    float* Yf   = sm;                 // 16384 (256 x 64)
    float* Lg   = sm + 16384;         // 7168  (32 x 224)
    float* Ys   = sm + 23552;         // 2176  (32 x 68)
    float* Ld   = sm + 25728;         // 1056  (32 x 33)
    float* rd   = sm + 26784;         // 256
    float* tile = sm + 27040;         // 1056

    const float* M  = g_M + (size_t)b * NV * NV;
    const float* Ab = A + (size_t)b * MCON * NV;
    float2* Y2 = (float2*)Yf;
    float4* Yf4 = (float4*)Yf;
    const float4* Ys4 = (const float4*)Ys;

    if (tid < NV) rd[tid] = 1.0f / M[(size_t)tid*NV + tid];
    if (g < 8) {
        for (int idx = tid; idx < 16384; idx += 1024) {
            const int i = idx >> 6, jj = idx & 63;
            Yf[idx] = Ab[(size_t)(g*64 + jj)*NV + i];
        }
    } else {
        for (int idx = tid; idx < 16384; idx += 1024) {
            const int i = idx >> 6, jj = idx & 63;
            Yf[idx] = (jj == 0) ? qv[b*NV + i] : 0.0f;
        }
    }
    __syncthreads();

    const int qd = tid >> 5, c2 = tid & 31;
    const int rowg = tid >> 4, colg = tid & 15;

    for (int p = 0; p < 8; p++) {
        const int P0 = 32 * p;
        {
            const int j = tid >> 5, i2 = tid & 31;
            Ld[j*33 + i2] = M[(size_t)(P0 + j)*NV + P0 + i2];
        }
        __syncthreads();

        for (int li = 0; li < 32; li++) {
            const int i = P0 + li;
            float2 yv = Y2[i*32 + c2];
            const float sc = rd[i];
            yv.x *= sc; yv.y *= sc;
            if (qd > li) {
                const float lv = Ld[li*33 + qd];
                float2 t = Y2[(P0 + qd)*32 + c2];
                t.x = fmaf(-lv, yv.x, t.x);
                t.y = fmaf(-lv, yv.y, t.y);
                Y2[(P0 + qd)*32 + c2] = t;
            }
            __syncthreads();
        }

        if (p < 7) {
            const int R = 224 - 32*p;
            for (int e = tid; e < 2048; e += 1024) {
                const int k = e >> 6, j = e & 63;
                Ys[k*68 + j] = Yf[(P0 + k)*64 + j] * rd[P0 + k];
            }
            for (int e = tid; e < 32*R; e += 1024) {
                const int k = e / R, ir = e - k*R;
                Lg[k*224 + ir] = M[(size_t)(P0 + k)*NV + P0 + 32 + ir];
            }
            __syncthreads();

#pragma unroll
            for (int rrr = 0; rrr < 4; rrr++) {
                const int i2r2 = rowg + 64*rrr;
                if (i2r2 < R) {
                    const int i2 = P0 + 32 + i2r2;
                    float4 a = Yf4[i2*16 + colg];
#pragma unroll
                    for (int k = 0; k < 32; k++) {
                        const float lv = Lg[k*224 + i2r2];
                        const float4 yv = Ys4[k*17 + colg];
                        a.x = fmaf(-lv, yv.x, a.x);
                        a.y = fmaf(-lv, yv.y, a.y);
                        a.z = fmaf(-lv, yv.z, a.z);
                        a.w = fmaf(-lv, yv.w, a.w);
                    }
                    Yf4[i2*16 + colg] = a;
                }
            }
            __syncthreads();
        }
    }

    for (int idx = tid; idx < 16384; idx += 1024)
        Yf[idx] *= rd[idx >> 6];
    __syncthreads();

    if (g < 8) {
        float* Ct = g_Ct + (size_t)b * MCON * NV;
        const int ty = tid >> 5, tx = tid & 31;
        for (int i0 = 0; i0 < 256; i0 += 32) {
            for (int j0 = 0; j0 < 64; j0 += 32) {
                tile[ty*33 + tx] = Yf[(i0 + ty)*64 + j0 + tx];
                __syncthreads();
                Ct[(size_t)(g*64 + j0 + ty)*NV + i0 + tx] = tile[tx*33 + ty];
                __syncthreads();
            }
        }
    } else {
        if (tid < NV) g_cq[b*NV + tid] = Yf[tid*64 + 0];
    }
}

// ---------------------------------------------------------------------------
// z0: z0 = -Ct cq. One block per batch.
// ---------------------------------------------------------------------------
__global__ void __launch_bounds__(256) z0_kernel()
{
    const int b = blockIdx.x, tid = threadIdx.x;
    __shared__ float cqs[256];
    cqs[tid] = g_cq[b*NV + tid];
    __syncthreads();
    const float4* Ct4 = (const float4*)(g_Ct + (size_t)b * MCON * NV);
    const float4* cq4 = (const float4*)cqs;
    for (int m = tid; m < MCON; m += 256) {
        float4 a = {0.f, 0.f, 0.f, 0.f};
#pragma unroll 8
        for (int k4 = 0; k4 < 64; k4++)
            dot4(a, Ct4[(size_t)m*64 + k4], cq4[k4]);
        g_z0[b*MCON + m] = -((a.x + a.y) + (a.z + a.w));
    }
}

__global__ void noop_kernel() {}

// ---------------------------------------------------------------------------
// admm3: 2-CTA cluster per batch, 1024 thr, 100 iterations per launch.
// Phase 1: partial t = C[:,own] w[own]  (own Ct rows; no w exchange)
// Exchange 256-float partial t via DSMEM, ONE cluster barrier/iter.
// Phase 2: z~[own] = z0 + C[:,own]^T t  (same Ct rows) + elementwise.
// ---------------------------------------------------------------------------
__global__ void __launch_bounds__(1024, 1) __cluster_dims__(2, 1, 1)
admm3_kernel(const float* __restrict__ l, const float* __restrict__ u, int phase)
{
    const int b = blockIdx.x >> 1, r = blockIdx.x & 1;
    const int tid = threadIdx.x;
    extern __shared__ float sh[];
    float* Ct_s = sh;                 // 196 rows x 260 floats (stride 65 f4)
    float* red  = sh + 50960;         // 4096
    float* w_s  = sh + 55056;         // 256 (own m half)
    float* t_s  = sh + 55312;         // 256 (combined t)
    float* t_pr = sh + 55568;         // 2 x 256 (peer partial, double buffer)
    // total 56080 floats = 224320 B

    const float RHO = 0.1f, ALPHA = 1.6f, OMA = -0.6f;
    const float4* Ct4 = (const float4*)(g_Ct + (size_t)b * MCON * NV
                                             + (size_t)(r * 256) * NV);
    float4* Cs4 = (float4*)Ct_s;
    float4* red4 = (float4*)red;
    const float4* ts4 = (const float4*)t_s;

    // cache own Ct rows [0,196) at stride 65 f4
    for (int i4 = tid; i4 < 196*64; i4 += 1024) {
        const int row = i4 >> 6, k4 = i4 & 63;
        Cs4[row*65 + k4] = Ct4[row*64 + k4];
    }

    const int mi = tid >> 2, qu = tid & 3;     // phase-2 map
    const int mg = r*256 + mi;
    const bool own = (qu == 0);
    const int k4g = tid & 63, gg = tid >> 6;   // phase-1 map (16 groups x 64 f4)

    float* st = g_state + (size_t)b * 2048;
    float sacc = 0.f, z_r = 0.f, y_r = 0.f, l_r = 0.f, u_r = 0.f, z0_r = 0.f;
    if (own) {
        l_r = l[b*MCON + mg]; u_r = u[b*MCON + mg];
        z0_r = g_z0[b*MCON + mg];
        if (phase) { sacc = st[mg]; z_r = st[512 + mg]; y_r = st[1024 + mg]; }
        w_s[mi] = fmaf(RHO, z_r, -y_r);
    }
    uint32_t ra_t0 = 0, ra_t1 = 0;
    if (tid < 256) {
        const uint32_t peer = (uint32_t)(r ^ 1);
        ra_t0 = mapa_u32((uint32_t)__cvta_generic_to_shared(t_pr + tid), peer);
        ra_t1 = mapa_u32((uint32_t)__cvta_generic_to_shared(t_pr + 256 + tid), peer);
    }
    __syncthreads();

    for (int it = 0; it < 100; it++) {
        // ---- phase 1: partial t over own m columns ----
        float4 a = {0.f, 0.f, 0.f, 0.f};
#pragma unroll
        for (int j = 0; j < 16; j++) {
            const int m = gg + 16*j;
            const float wv = w_s[m];
            float4 cv = (m < 196) ? Cs4[m*65 + k4g] : __ldcg(Ct4 + m*64 + k4g);
            fma4(a, cv, wv);
        }
        red4[gg*64 + k4g] = a;
        __syncthreads();

        float p = 0.f;
        if (tid < 256) {
#pragma unroll
            for (int g2 = 0; g2 < 16; g2++) p += red[g2*256 + tid];
            if (it & 1) st_cluster_f32(ra_t1, p);
            else        st_cluster_f32(ra_t0, p);
        }
        CLUSTER_ARRIVE(); CLUSTER_WAIT();
        if (tid < 256)
            t_s[tid] = p + t_pr[(it & 1)*256 + tid];
        __syncthreads();

        // ---- phase 2: z~[own m] = z0 + column dot (4-thread k-split) ----
        float4 a2 = {0.f, 0.f, 0.f, 0.f};
        if (mi < 196) {
            const float4* col = Cs4 + mi*65 + qu*16;
            const float4* tq = ts4 + qu*16;
#pragma unroll
            for (int t = 0; t < 16; t++) {
                const int t2 = (t + 2*qu) & 15;     // conflict-free rotation
                dot4(a2, col[t2], tq[t2]);
            }
        } else {
            const float4* col = Ct4 + mi*64 + qu*16;
            const float4* tq = ts4 + qu*16;
#pragma unroll
            for (int t = 0; t < 16; t++)
                dot4(a2, __ldcg(col + t), tq[t]);
        }
        float s = (a2.x + a2.y) + (a2.z + a2.w);
        s += __shfl_xor_sync(0xffffffffu, s, 1);
        s += __shfl_xor_sync(0xffffffffu, s, 2);
        if (own) {
            const float w_r = w_s[mi];
            sacc = fmaf(OMA, sacc, ALPHA * w_r);
            float zt = z0_r + s;
            float zr = fmaf(ALPHA, zt, OMA * z_r);
            float zc = fminf(fmaxf(fmaf(y_r, 10.0f, zr), l_r), u_r);  // 1/RHO=10
            y_r = fmaf(RHO, zr - zc, y_r);
            z_r = zc;
            w_s[mi] = fmaf(RHO, z_r, -y_r);
        }
        __syncthreads();
    }

    if (own) {
        if (phase == 0) {
            st[mg] = sacc; st[512 + mg] = z_r; st[1024 + mg] = y_r;
        } else {
            st[mg] = sacc;
        }
    }
}

// ---------------------------------------------------------------------------
// finish: v = A^T sacc - q; solve M x = v; out = x. One block per batch.
// ---------------------------------------------------------------------------
__global__ void __launch_bounds__(1024) finish_kernel(const float* __restrict__ A,
                                                      const float* __restrict__ qv,
                                                      float* __restrict__ out)
{
    const int b = blockIdx.x, tid = threadIdx.x;
    __shared__ float sacc_s[512];
    __shared__ float red[4096];
    __shared__ float vv[256];
    __shared__ float rds[256];
    const float* st = g_state + (size_t)b * 2048;
    const float* M = g_M + (size_t)b * NV * NV;
    const float* W = g_W + (size_t)b * NV * NV;

    if (tid < 512) sacc_s[tid] = st[tid];
    if (tid < NV) rds[tid] = 1.0f / M[(size_t)tid*NV + tid];
    __syncthreads();

    const float4* A4g = (const float4*)(A + (size_t)b * MCON * NV);
    const int ms = tid >> 6, jg = tid & 63;
    float4 acc = {0,0,0,0};
    for (int m = ms; m < MCON; m += 16)
        fma4(acc, __ldcg(A4g + (size_t)m*64 + jg), sacc_s[m]);
    ((float4*)red)[ms*64 + jg] = acc;
    __syncthreads();
    if (tid < NV) {
        float v = -qv[b*NV + tid];
#pragma unroll
        for (int s = 0; s < 16; s++) v += red[s*256 + tid];
        vv[tid] = v;
    }
    __syncthreads();

    for (int j = 0; j < NV; j++) {
        float yj = vv[j] * rds[j];
        __syncthreads();
        if (tid < NV && tid > j)
            vv[tid] = fmaf(-M[(size_t)j*NV + tid], yj, vv[tid]);
        __syncthreads();
    }
    if (tid < NV) vv[tid] *= rds[tid];
    __syncthreads();
    for (int j = NV - 1; j >= 0; j--) {
        float xj = vv[j] * rds[j];
        __syncthreads();
        if (tid < j)
            vv[tid] = fmaf(-W[(size_t)j*NV + tid], xj, vv[tid]);
        __syncthreads();
    }
    if (tid < NV)
        out[b*NV + tid] = vv[tid] * rds[tid];
}

// ---------------------------------------------------------------------------
extern "C" void kernel_launch(void* const* d_in, const int* in_sizes, int n_in,
                              void* d_out, int out_size)
{
    const float* P = (const float*)d_in[0];
    const float* q = (const float*)d_in[1];
    const float* A = (const float*)d_in[2];
    const float* l = (const float*)d_in[3];
    const float* u = (const float*)d_in[4];
    float* out = (float*)d_out;

    const int CHOL_SMEM   = 12512 * 4;       // 50048
    const int CSOLVE_SMEM = 28096 * 4;       // 112384
    const int ADMM_SMEM   = 56080 * 4;       // 224320
    cudaFuncSetAttribute(setup2_kernel, cudaFuncAttributeMaxDynamicSharedMemorySize, CHOL_SMEM);
    cudaFuncSetAttribute(csolve_kernel, cudaFuncAttributeMaxDynamicSharedMemorySize, CSOLVE_SMEM);
    cudaFuncSetAttribute(admm3_kernel,  cudaFuncAttributeMaxDynamicSharedMemorySize, ADMM_SMEM);

    setup1_kernel<<<dim3(10, NBAT), 256>>>(A, P);
    setup2_kernel<<<NBAT, 1024, CHOL_SMEM>>>();
    csolve_kernel<<<dim3(9, NBAT), 1024, CSOLVE_SMEM>>>(A, q);
    z0_kernel<<<NBAT, 256>>>();
    admm3_kernel<<<2 * NBAT, 1024, ADMM_SMEM>>>(l, u, 0);
    noop_kernel<<<1, 32>>>();
    admm3_kernel<<<2 * NBAT, 1024, ADMM_SMEM>>>(l, u, 1);
    finish_kernel<<<NBAT, 1024>>>(A, q, out);
}